// round 15
// baseline (speedup 1.0000x reference)
#include <cuda_runtime.h>
#include <cuda_fp16.h>
#include <stdint.h>

// HybridMixSTEDecoder: 5 disjoint-group GEMMs (27648x512 @ 512xN_i) + bias,
// scattered into out[b, tp*9+p, joint, c]. Groups disjoint -> count/div identity.
//
// Single-pass fp16 mma.sync (A, B RN-rounded fp16, fp32 accum; rel_err ~3e-4).
// KEY CHANGE (L1tex wavefront reduction): 32 M-rows per warp so each B ldmatrix
// tile is shared by TWO 16-row A fragments (B wf/row halves). A goes through
// smem via cp.async (K-chunk 32, 3 stages, wait_group 1) so no A register
// buffer is needed (acc[2][NT][4] fits in 128 regs).
// Grid (variant, m-block): CTAs sharing token rows are schedule-adjacent.

// Regions: v0..v3 = g0,g1,g3,g4 (NPAD 88); v4,v5 = g2 halves (NPAD 72).
// Per chunk32: NT*4 tile-lines of 128B (tile = 8 n-rows x 16B, line-packed).
// u32 sizes: 88*256 = 22528; 72*256 = 18432. Total 126976 u32.
static __device__ __align__(16) uint32_t g_B[126976];

// ---------------- helpers ----------------
static __device__ __forceinline__ uint32_t s2u(const void* p) {
    uint32_t a;
    asm("{ .reg .u64 t; cvta.to.shared.u64 t, %1; cvt.u32.u64 %0, t; }"
        : "=r"(a) : "l"(p));
    return a;
}
static __device__ __forceinline__ uint32_t f16x2_rn(float lo, float hi) {
    uint32_t r; asm("cvt.rn.f16x2.f32 %0, %1, %2;" : "=r"(r) : "f"(hi), "f"(lo));
    return r;  // low half = lo, high half = hi
}
static __device__ __forceinline__ float4 lds128(uint32_t a) {
    float4 v;
    asm volatile("ld.shared.v4.f32 {%0,%1,%2,%3}, [%4];"
        : "=f"(v.x), "=f"(v.y), "=f"(v.z), "=f"(v.w) : "r"(a));
    return v;
}
static __device__ __forceinline__ void ldsm_x4(uint32_t* r, uint32_t addr) {
    asm volatile("ldmatrix.sync.aligned.m8n8.x4.shared.b16 {%0,%1,%2,%3}, [%4];"
        : "=r"(r[0]), "=r"(r[1]), "=r"(r[2]), "=r"(r[3]) : "r"(addr));
}
static __device__ __forceinline__ void ldsm_x2(uint32_t* r, uint32_t addr) {
    asm volatile("ldmatrix.sync.aligned.m8n8.x2.shared.b16 {%0,%1}, [%2];"
        : "=r"(r[0]), "=r"(r[1]) : "r"(addr));
}
static __device__ __forceinline__ void mma_f16(float* d, const uint32_t* a,
                                               const uint32_t* b) {
    asm volatile(
        "mma.sync.aligned.m16n8k16.row.col.f32.f16.f16.f32 "
        "{%0,%1,%2,%3}, {%4,%5,%6,%7}, {%8,%9}, {%0,%1,%2,%3};"
        : "+f"(d[0]), "+f"(d[1]), "+f"(d[2]), "+f"(d[3])
        : "r"(a[0]), "r"(a[1]), "r"(a[2]), "r"(a[3]), "r"(b[0]), "r"(b[1]));
}
static __device__ __forceinline__ void cp16(uint32_t dst, const void* src, int pred) {
    asm volatile(
        "{\n\t.reg .pred p;\n\tsetp.ne.b32 p, %0, 0;\n\t"
        "@p cp.async.cg.shared.global [%1], [%2], 16;\n\t}"
        :: "r"(pred), "r"(dst), "l"(src));
}

// ---------------- prep: W (f32) -> fp16 tile-packed per chunk32 -------------
// Thread (grow, k4): kc32 = k>>5, jj = (k>>4)&1, t = (k>>2)&3.
//   h01 = f16(k,k+1)   -> tile (ntile, jj, ku=0), slot (n&7, t)
//   h23 = f16(k+2,k+3) -> tile (ntile, jj, ku=1)
// line index within stage = (n>>3)*4 + jj*2 + ku.
__global__ void __launch_bounds__(256) prep_B(
    const float* __restrict__ W0, const float* __restrict__ W1,
    const float* __restrict__ W2, const float* __restrict__ W3,
    const float* __restrict__ W4)
{
    int idx = blockIdx.x * 256 + threadIdx.x;   // one thread per (grow, k4)
    if (idx >= 496 * 128) return;
    int grow = idx >> 7;
    int k = (idx & 127) << 2;

    const float* Wg;
    int n, n_src, npad, base, Ng;
    if (grow < 352) {                        // v0..v3: NPAD 88
        int v = grow / 88;
        n = grow - v * 88;
        n_src = n;
        npad = 88;
        base = v * 22528;
        Ng = 81;
        Wg = (v == 0) ? W0 : (v == 1) ? W1 : (v == 2) ? W3 : W4;
    } else if (grow < 424) {                 // v4: g2 half 0
        n = grow - 352; n_src = n;
        npad = 72; base = 90112; Ng = 135; Wg = W2;
    } else {                                 // v5: g2 half 1
        n = grow - 424; n_src = n + 72;
        npad = 72; base = 108544; Ng = 135; Wg = W2;
    }

    float4 v4v = make_float4(0.f, 0.f, 0.f, 0.f);
    if (n_src < Ng) v4v = *(const float4*)(Wg + n_src * 512 + k);

    uint32_t h01 = f16x2_rn(v4v.x, v4v.y);
    uint32_t h23 = f16x2_rn(v4v.z, v4v.w);

    int kc = k >> 5, jj = (k >> 4) & 1, t = (k >> 2) & 3;
    uint32_t* dst = g_B + base + kc * (npad * 16)
                  + ((n >> 3) * 4 + jj * 2) * 32 + (n & 7) * 4 + t;
    dst[0]  = h01;   // ku = 0
    dst[32] = h23;   // ku = 1
}

// ---------------- fused core ----------------
// Smem: 3 stages of [A: 256 rows x 128B raw f32 (unit swizzle u^((row&1)<<2))]
// then 3 stages of [B: NT*4 tile-lines x 128B].
template<int NPAD, int GS, int CO>
static __device__ __forceinline__ void decode_core(
    const float* __restrict__ tokens,
    const uint32_t* __restrict__ Breg,     // region base in g_B
    const float* __restrict__ bias,
    float* __restrict__ out,
    int gidx, int jb3)
{
    constexpr int NT    = NPAD / 8;
    constexpr int QQ    = NT / 2;
    constexpr int ODD   = NT & 1;
    constexpr int NREAL = (GS == 5) ? 135 : 81;
    constexpr int ABS   = 32768;               // A stage: 256 rows x 128B
    constexpr int BBS   = NPAD * 64;           // B stage bytes
    constexpr int BOFF  = 3 * ABS;
    constexpr int NB16  = NPAD * 4;            // B cp.async 16B ops per stage

    extern __shared__ char smem[];
    const uint32_t su = s2u(smem);

    const int tid  = threadIdx.x;
    const int wid  = tid >> 5;
    const int lane = tid & 31;

    const int m0 = blockIdx.y * 256;
    const float* Abase = tokens + (size_t)m0 * 2560 + gidx * 512;

    // ---- A producer: 8 iters, row = (tid>>3) + 32*i, 8 lanes = 128B line ----
    const int prow = tid >> 3;
    const int pu   = tid & 7;
    const float* asrc0 = Abase + (size_t)prow * 2560 + pu * 4;
    const uint32_t adst0 = su + (uint32_t)(prow * 128
                         + ((pu ^ ((prow & 1) << 2)) << 4));

    // ---- A consumer (LDS.128): warp rows 32*wid + 16f + g (+8) ----
    const int g   = lane >> 2;
    const int tig = lane & 3;
    const int xr  = (g & 1) << 2;              // row parity (base rows even)
    const uint32_t acA = su + (uint32_t)((32 * wid + g) * 128);

    // ---- B consumer (ldmatrix over tile-lines) ----
    const uint32_t blx  = (uint32_t)(((((lane >> 4) & 1) << 2)
                        + ((lane >> 3) & 1)) * 128 + (lane & 7) * 16);
    const uint32_t blx2 = (uint32_t)((((lane >> 3) & 1)) * 128 + (lane & 7) * 16);

    float acc[2][NT][4];
    #pragma unroll
    for (int f = 0; f < 2; f++)
        #pragma unroll
        for (int t = 0; t < NT; t++)
            #pragma unroll
            for (int q = 0; q < 4; q++) acc[f][t][q] = 0.f;

    // ---- prologue: chunks 0,1 as 2 commit groups ----
    #pragma unroll
    for (int c = 0; c < 2; c++) {
        #pragma unroll
        for (int i = 0; i < 8; i++)
            cp16(adst0 + c * ABS + i * 4096,
                 asrc0 + (size_t)i * 81920 + c * 32, 1);
        const uint32_t* bsrc = Breg + c * (NPAD * 16);
        #pragma unroll
        for (int it = 0; it < 2; it++) {
            int idx = tid + it * 256;
            cp16(su + BOFF + c * BBS + (uint32_t)(idx * 16), bsrc + idx * 4,
                 idx < NB16);
        }
        asm volatile("cp.async.commit_group;" ::: "memory");
    }

    int s = 0;
    #pragma unroll 1
    for (int kc = 0; kc < 16; kc++) {
        // chunk kc landed when <=1 group pending
        asm volatile("cp.async.wait_group 1;" ::: "memory");
        __syncthreads();

        // issue chunk kc+2 into stage (s+2)%3 (readers finished last iter)
        {
            const int c = kc + 2;
            const int pred = (c < 16);
            const int s2 = (s == 0) ? 2 : s - 1;
            #pragma unroll
            for (int i = 0; i < 8; i++)
                cp16(adst0 + s2 * ABS + i * 4096,
                     asrc0 + (size_t)i * 81920 + c * 32, pred);
            const uint32_t* bsrc = Breg + c * (NPAD * 16);
            #pragma unroll
            for (int it = 0; it < 2; it++) {
                int idx = tid + it * 256;
                cp16(su + BOFF + s2 * BBS + (uint32_t)(idx * 16), bsrc + idx * 4,
                     pred && (idx < NB16));
            }
            asm volatile("cp.async.commit_group;" ::: "memory");
        }

        // compute on stage s: 2 k16 fragments (jj), B shared across both f
        const uint32_t aS = acA + (uint32_t)(s * ABS);
        const uint32_t bB = su + BOFF + (uint32_t)(s * BBS);
        #pragma unroll
        for (int jj = 0; jj < 2; jj++) {
            const uint32_t u = (uint32_t)(((4 * jj + tig) ^ xr) << 4);
            // A fragments for both 16-row halves (rows +0/+8 and +16/+24)
            float4 v1 = lds128(aS + u);
            float4 v2 = lds128(aS + 1024 + u);
            float4 v3 = lds128(aS + 2048 + u);
            float4 v4 = lds128(aS + 3072 + u);
            uint32_t a0[4], a1[4];
            a0[0] = f16x2_rn(v1.x, v1.y);
            a0[2] = f16x2_rn(v1.z, v1.w);
            a0[1] = f16x2_rn(v2.x, v2.y);
            a0[3] = f16x2_rn(v2.z, v2.w);
            a1[0] = f16x2_rn(v3.x, v3.y);
            a1[2] = f16x2_rn(v3.z, v3.w);
            a1[1] = f16x2_rn(v4.x, v4.y);
            a1[3] = f16x2_rn(v4.z, v4.w);
            const uint32_t bj = bB + (uint32_t)(jj * 256);
            #pragma unroll
            for (int q = 0; q < QQ; q++) {
                uint32_t bh[4];
                ldsm_x4(bh, bj + (uint32_t)(q * 1024) + blx);
                mma_f16(acc[0][2 * q],     a0, bh);
                mma_f16(acc[0][2 * q + 1], a0, bh + 2);
                mma_f16(acc[1][2 * q],     a1, bh);
                mma_f16(acc[1][2 * q + 1], a1, bh + 2);
            }
            if (ODD) {
                uint32_t bh[2];
                ldsm_x2(bh, bj + (uint32_t)((NT - 1) * 512) + blx2);
                mma_f16(acc[0][NT - 1], a0, bh);
                mma_f16(acc[1][NT - 1], a1, bh);
            }
        }
        s = (s == 2) ? 0 : s + 1;
    }

    // ---- epilogue: bias + scatter ----
    int   coff[NT][2];
    float cb[NT][2];
    #pragma unroll
    for (int t = 0; t < NT; t++) {
        #pragma unroll
        for (int h = 0; h < 2; h++) {
            int o = CO + 8 * t + 2 * tig + h;
            if (o < NREAL) {
                int p   = o / (GS * 3);
                int rem = o - p * (GS * 3);
                int joff = (GS == 5) ? ((rem < 3) ? rem : rem + 18) : (jb3 + rem);
                coff[t][h] = p * 51 + joff;
                cb[t][h]   = bias[o];
            } else {
                coff[t][h] = -1;
                cb[t][h]   = 0.f;
            }
        }
    }

    #pragma unroll
    for (int f = 0; f < 2; f++) {
        #pragma unroll
        for (int half = 0; half < 2; half++) {
            int m  = m0 + 32 * wid + 16 * f + g + 8 * half;
            int b  = m / 27;
            int tp = m - b * 27;
            size_t obase = (size_t)b * 12393 + (size_t)tp * 459;
            #pragma unroll
            for (int t = 0; t < NT; t++) {
                float v0 = acc[f][t][2 * half];
                float v1 = acc[f][t][2 * half + 1];
                if (coff[t][0] >= 0) out[obase + coff[t][0]] = v0 + cb[t][0];
                if (coff[t][1] >= 0) out[obase + coff[t][1]] = v1 + cb[t][1];
            }
        }
    }
}

// One fused kernel. blockIdx.x = variant: 0..3 -> groups 0,1,3,4 (NPAD=88);
// 4,5 -> group 2 halves (NPAD=72). blockIdx.y = m-block of 256 rows (same
// token rows across all 6 variants -> L2 reuse).
__global__ void __launch_bounds__(256, 2) dec_all(
    const float* __restrict__ tokens,
    const float* __restrict__ b0, const float* __restrict__ b1,
    const float* __restrict__ b2, const float* __restrict__ b3,
    const float* __restrict__ b4,
    float* __restrict__ out)
{
    int y = blockIdx.x;
    if (y < 4) {
        int gidx, jb3;
        const float* bias;
        switch (y) {
            case 0:  gidx = 0; jb3 = 3;  bias = b0; break;
            case 1:  gidx = 1; jb3 = 12; bias = b1; break;
            case 2:  gidx = 3; jb3 = 33; bias = b3; break;
            default: gidx = 4; jb3 = 42; bias = b4; break;
        }
        decode_core<88, 3, 0>(tokens, g_B + y * 22528, bias, out, gidx, jb3);
    } else if (y == 4) {
        decode_core<72, 5, 0>(tokens, g_B + 90112, b2, out, 2, 0);
    } else {
        decode_core<72, 5, 72>(tokens, g_B + 108544, b2, out, 2, 0);
    }
}

extern "C" void kernel_launch(void* const* d_in, const int* in_sizes, int n_in,
                              void* d_out, int out_size) {
    const float* tokens = (const float*)d_in[0];
    const float* W[5];
    const float* B[5];
    for (int i = 0; i < 5; i++) {
        W[i] = (const float*)d_in[1 + 2 * i];
        B[i] = (const float*)d_in[2 + 2 * i];
    }
    float* out = (float*)d_out;

    // dyn smem: 3 A stages (32KB) + 3 B stages (<=5632B) = 115200 B
    // -> 2 CTAs/SM (230400 <= 233472).
    const int smem_sz = 3 * 32768 + 3 * 88 * 64;
    cudaFuncSetAttribute(dec_all, cudaFuncAttributeMaxDynamicSharedMemorySize, smem_sz);

    prep_B<<<(496 * 128 + 255) / 256, 256>>>(W[0], W[1], W[2], W[3], W[4]);
    dec_all<<<dim3(6, 108), 256, smem_sz>>>(tokens, B[0], B[1], B[2], B[3], B[4], out);
}

// round 16
// speedup vs baseline: 1.1933x; 1.1933x over previous
#include <cuda_runtime.h>
#include <cuda_fp16.h>
#include <stdint.h>

// HybridMixSTEDecoder: 5 disjoint-group GEMMs (27648x512 @ 512xN_i) + bias,
// scattered into out[b, tp*9+p, joint, c]. Groups disjoint -> count/div identity.
//
// Single-pass fp16 mma.sync (A, B RN-rounded fp16, fp32 accum; rel_err ~3e-4).
// Same per-warp structure as the 85.5us best (register-buffered A direct from
// gmem, K-chunk 64, line-packed B tiles via cp.async double-buffer), but with
// SMALL CTAs: M-tile 64, 128 threads, 4 CTAs/SM. Same 16 warps/SM in steady
// state; CTA lifetime halves -> end-of-kernel drain tail halves.

// Regions: v0..v3 = g0,g1,g3,g4 (NPAD 88); v4,v5 = g2 halves (NPAD 72).
// u32 sizes: 88*256 = 22528; 72*256 = 18432. Total 126976 u32.
static __device__ __align__(16) uint32_t g_B[126976];

// ---------------- helpers ----------------
static __device__ __forceinline__ uint32_t s2u(const void* p) {
    uint32_t a;
    asm("{ .reg .u64 t; cvta.to.shared.u64 t, %1; cvt.u32.u64 %0, t; }"
        : "=r"(a) : "l"(p));
    return a;
}
static __device__ __forceinline__ uint32_t f16x2_rn(float lo, float hi) {
    uint32_t r; asm("cvt.rn.f16x2.f32 %0, %1, %2;" : "=r"(r) : "f"(hi), "f"(lo));
    return r;  // low half = lo, high half = hi
}
static __device__ __forceinline__ void ldsm_x4(uint32_t* r, uint32_t addr) {
    asm volatile("ldmatrix.sync.aligned.m8n8.x4.shared.b16 {%0,%1,%2,%3}, [%4];"
        : "=r"(r[0]), "=r"(r[1]), "=r"(r[2]), "=r"(r[3]) : "r"(addr));
}
static __device__ __forceinline__ void ldsm_x2(uint32_t* r, uint32_t addr) {
    asm volatile("ldmatrix.sync.aligned.m8n8.x2.shared.b16 {%0,%1}, [%2];"
        : "=r"(r[0]), "=r"(r[1]) : "r"(addr));
}
static __device__ __forceinline__ void mma_f16(float* d, const uint32_t* a,
                                               const uint32_t* b) {
    asm volatile(
        "mma.sync.aligned.m16n8k16.row.col.f32.f16.f16.f32 "
        "{%0,%1,%2,%3}, {%4,%5,%6,%7}, {%8,%9}, {%0,%1,%2,%3};"
        : "+f"(d[0]), "+f"(d[1]), "+f"(d[2]), "+f"(d[3])
        : "r"(a[0]), "r"(a[1]), "r"(a[2]), "r"(a[3]), "r"(b[0]), "r"(b[1]));
}
static __device__ __forceinline__ void cp16(uint32_t dst, const void* src, int pred) {
    asm volatile(
        "{\n\t.reg .pred p;\n\tsetp.ne.b32 p, %0, 0;\n\t"
        "@p cp.async.cg.shared.global [%1], [%2], 16;\n\t}"
        :: "r"(pred), "r"(dst), "l"(src));
}

// ---------------- prep: W (f32) -> fp16 line-packed ldmatrix tiles ----------
// (identical to the proven 85.5us version)
__global__ void __launch_bounds__(256) prep_B(
    const float* __restrict__ W0, const float* __restrict__ W1,
    const float* __restrict__ W2, const float* __restrict__ W3,
    const float* __restrict__ W4)
{
    int idx = blockIdx.x * 256 + threadIdx.x;   // one thread per (grow, k4)
    if (idx >= 496 * 128) return;
    int grow = idx >> 7;
    int k = (idx & 127) << 2;

    const float* Wg;
    int n, n_src, npad, base, Ng;
    if (grow < 352) {                        // v0..v3: NPAD 88
        int v = grow / 88;
        n = grow - v * 88;
        n_src = n;
        npad = 88;
        base = v * 22528;
        Ng = 81;
        Wg = (v == 0) ? W0 : (v == 1) ? W1 : (v == 2) ? W3 : W4;
    } else if (grow < 424) {                 // v4: g2 half 0
        n = grow - 352; n_src = n;
        npad = 72; base = 90112; Ng = 135; Wg = W2;
    } else {                                 // v5: g2 half 1
        n = grow - 424; n_src = n + 72;
        npad = 72; base = 108544; Ng = 135; Wg = W2;
    }

    float4 v4v = make_float4(0.f, 0.f, 0.f, 0.f);
    if (n_src < Ng) v4v = *(const float4*)(Wg + n_src * 512 + k);

    uint32_t h01 = f16x2_rn(v4v.x, v4v.y);
    uint32_t h23 = f16x2_rn(v4v.z, v4v.w);

    int kc = k >> 6, j = (k >> 4) & 3, t = (k >> 2) & 3;
    uint32_t* dst = g_B + base + kc * (npad * 32) + (n >> 3) * 256
                  + (2 * j) * 32 + (n & 7) * 4 + t;
    dst[0]  = h01;   // unit 2j
    dst[32] = h23;   // unit 2j+1
}

// ---------------- fused core ----------------
// Smem: two B stages of NPAD*128 bytes, contents already in final tile order
// (contiguous copy from g_B). A never touches smem (register chunk buffer).
template<int NPAD, int GS, int CO>
static __device__ __forceinline__ void decode_core(
    const float* __restrict__ tokens,
    const uint32_t* __restrict__ Breg,     // region base in g_B
    const float* __restrict__ bias,
    float* __restrict__ out,
    int gidx, int jb3)
{
    constexpr int NT    = NPAD / 8;
    constexpr int PAIRS = NT / 2;
    constexpr int ODD   = NT & 1;
    constexpr int NREAL = (GS == 5) ? 135 : 81;
    constexpr int BB    = NPAD * 128;          // B stage bytes (one chunk)
    constexpr int NB8   = NPAD * 8;            // cp.async 16B ops
    constexpr int CPIT  = (NB8 + 127) / 128;

    extern __shared__ char smem[];
    const uint32_t su = s2u(smem);

    const int tid  = threadIdx.x;
    const int wid  = tid >> 5;                 // 0..3
    const int lane = tid & 31;

    const int m0 = blockIdx.y * 64;

    // A direct-load geometry with the k-permute: lane (r = lane>>2, tig = lane&3)
    // loads float4 at (row r, k = 16j + 4*tig) and (row r+8, same k).
    const float* aw = tokens
        + (size_t)(m0 + 16 * wid + (lane >> 2)) * 2560
        + gidx * 512 + (lane & 3) * 4;

    // B ldmatrix lane addressing (line-packed tiles):
    //   x4 addr = bBase + p*2048 + j*256 + bl
    const uint32_t bl  = (uint32_t)((((lane >> 4) & 1) << 10)
                       + (((lane >> 3) & 1) << 7) + ((lane & 7) << 4));
    const uint32_t bl2 = (uint32_t)((((lane >> 3) & 1) << 7) + ((lane & 7) << 4));

    float acc[NT][4];
    #pragma unroll
    for (int t = 0; t < NT; t++)
        #pragma unroll
        for (int q = 0; q < 4; q++) acc[t][q] = 0.f;

    // Full-chunk A register buffer (compile-time indices only).
    float4 ra[8];
    #pragma unroll
    for (int j = 0; j < 4; j++) {
        ra[2 * j]     = *(const float4*)(aw + j * 16);
        ra[2 * j + 1] = *(const float4*)(aw + j * 16 + 20480);
    }
    // B(0) cp.async: contiguous copy (layout pre-baked in prep_B)
    {
        const char* bsrc = (const char*)Breg;
        #pragma unroll
        for (int jj = 0; jj < CPIT; jj++) {
            int idx = tid + jj * 128;
            cp16(su + (uint32_t)(idx * 16), bsrc + idx * 16, idx < NB8);
        }
        asm volatile("cp.async.commit_group;" ::: "memory");
    }

    #pragma unroll 1
    for (int kc = 0; kc < 8; kc++) {
        const int s = kc & 1;

        // B(kc) ready; publish stage s
        asm volatile("cp.async.wait_group 0;" ::: "memory");
        __syncthreads();
        // issue B(kc+1) into stage s^1 (all warps are past reads of s^1)
        if (kc < 7) {
            const uint32_t bdst = su + (uint32_t)((s ^ 1) * BB);
            const char* bsrc = (const char*)(Breg + (kc + 1) * (NPAD * 32));
            #pragma unroll
            for (int jj = 0; jj < CPIT; jj++) {
                int idx = tid + jj * 128;
                cp16(bdst + (uint32_t)(idx * 16), bsrc + idx * 16, idx < NB8);
            }
            asm volatile("cp.async.commit_group;" ::: "memory");
        }

        const uint32_t bBase = su + (uint32_t)(s * BB);
        #pragma unroll
        for (int j = 0; j < 4; j++) {
            // convert current A fragment (permuted layout: float4 -> a0,a2)
            uint32_t ah[4];
            ah[0] = f16x2_rn(ra[2 * j].x,     ra[2 * j].y);
            ah[2] = f16x2_rn(ra[2 * j].z,     ra[2 * j].w);
            ah[1] = f16x2_rn(ra[2 * j + 1].x, ra[2 * j + 1].y);
            ah[3] = f16x2_rn(ra[2 * j + 1].z, ra[2 * j + 1].w);
            // refill this slot from chunk kc+1 (lookahead ~4 j-steps)
            if (kc < 7) {
                const float* ap = aw + (kc + 1) * 64 + j * 16;
                ra[2 * j]     = *(const float4*)(ap);
                ra[2 * j + 1] = *(const float4*)(ap + 20480);
            }
            // B fragments + MMAs (line-packed tiles)
            const uint32_t bj = bBase + (uint32_t)(j * 256);
            #pragma unroll
            for (int p = 0; p < PAIRS; p++) {
                uint32_t bh[4];
                ldsm_x4(bh, bj + (uint32_t)(p * 2048) + bl);
                mma_f16(acc[2 * p],     ah, bh);
                mma_f16(acc[2 * p + 1], ah, bh + 2);
            }
            if (ODD) {
                uint32_t bh[2];
                ldsm_x2(bh, bj + (uint32_t)(PAIRS * 2048) + bl2);
                mma_f16(acc[NT - 1], ah, bh);
            }
        }
    }

    // ---- epilogue: bias + scatter ----
    const int g   = lane >> 2;
    const int tig = lane & 3;

    int   coff[NT][2];
    float cb[NT][2];
    #pragma unroll
    for (int t = 0; t < NT; t++) {
        #pragma unroll
        for (int h = 0; h < 2; h++) {
            int o = CO + 8 * t + 2 * tig + h;
            if (o < NREAL) {
                int p   = o / (GS * 3);
                int rem = o - p * (GS * 3);
                int joff = (GS == 5) ? ((rem < 3) ? rem : rem + 18) : (jb3 + rem);
                coff[t][h] = p * 51 + joff;
                cb[t][h]   = bias[o];
            } else {
                coff[t][h] = -1;
                cb[t][h]   = 0.f;
            }
        }
    }

    #pragma unroll
    for (int half = 0; half < 2; half++) {
        int m  = m0 + 16 * wid + g + 8 * half;
        int b  = m / 27;
        int tp = m - b * 27;
        size_t obase = (size_t)b * 12393 + (size_t)tp * 459;
        #pragma unroll
        for (int t = 0; t < NT; t++) {
            float v0 = acc[t][2 * half];
            float v1 = acc[t][2 * half + 1];
            if (coff[t][0] >= 0) out[obase + coff[t][0]] = v0 + cb[t][0];
            if (coff[t][1] >= 0) out[obase + coff[t][1]] = v1 + cb[t][1];
        }
    }
}

// One fused kernel. blockIdx.x = variant: 0..3 -> groups 0,1,3,4 (NPAD=88);
// 4,5 -> group 2 halves (NPAD=72). blockIdx.y = m-block of 64 rows (same
// token rows across all 6 variants -> L2 reuse for g2 double-read + output
// merging). Small CTAs (128 thr, 4/SM) halve the end-of-kernel drain tail.
__global__ void __launch_bounds__(128, 4) dec_all(
    const float* __restrict__ tokens,
    const float* __restrict__ b0, const float* __restrict__ b1,
    const float* __restrict__ b2, const float* __restrict__ b3,
    const float* __restrict__ b4,
    float* __restrict__ out)
{
    int y = blockIdx.x;
    if (y < 4) {
        int gidx, jb3;
        const float* bias;
        switch (y) {
            case 0:  gidx = 0; jb3 = 3;  bias = b0; break;
            case 1:  gidx = 1; jb3 = 12; bias = b1; break;
            case 2:  gidx = 3; jb3 = 33; bias = b3; break;
            default: gidx = 4; jb3 = 42; bias = b4; break;
        }
        decode_core<88, 3, 0>(tokens, g_B + y * 22528, bias, out, gidx, jb3);
    } else if (y == 4) {
        decode_core<72, 5, 0>(tokens, g_B + 90112, b2, out, 2, 0);
    } else {
        decode_core<72, 5, 72>(tokens, g_B + 108544, b2, out, 2, 0);
    }
}

extern "C" void kernel_launch(void* const* d_in, const int* in_sizes, int n_in,
                              void* d_out, int out_size) {
    const float* tokens = (const float*)d_in[0];
    const float* W[5];
    const float* B[5];
    for (int i = 0; i < 5; i++) {
        W[i] = (const float*)d_in[1 + 2 * i];
        B[i] = (const float*)d_in[2 + 2 * i];
    }
    float* out = (float*)d_out;

    // dyn smem: 2 B stages of 88*128 = 22528 bytes max; 4 CTAs/SM -> 90112 B.
    const int smem_sz = 2 * 88 * 128;

    prep_B<<<(496 * 128 + 255) / 256, 256>>>(W[0], W[1], W[2], W[3], W[4]);
    dec_all<<<dim3(6, 432), 128, smem_sz>>>(tokens, B[0], B[1], B[2], B[3], B[4], out);
}